// round 10
// baseline (speedup 1.0000x reference)
#include <cuda_runtime.h>
#include <cstdint>

// out[s,b,o,hw] = sum_k adc_real[b,k,hw]*W[s*256+o,k] + adc_imag[b,k,hw]*W[s*256+o,256+k]
// GEMM D[512, 4*65536] = W[512,512] * X[512,*] via mma.sync tf32 HMMA.
// R10: CTA tile 256o x 256hw, 16 warps (4Mx4N), warp tile 64x64 -> 128B smem
// per MMA (crossbar at ~63% of tensor window) with 4 warps/SMSP for latency
// hiding. 3-stage cp.async W (pre-rounded, k-pair-permuted), register X fill
// (RNA tf32), direct STG.64 epilogue.

#define NFFT 256
#define HW   65536
#define KTOT 512
#define KC   32
#define MT   256
#define NT   256
#define NSTG 3
#define XP   264                 // xs pitch (floats): 264 mod 32 = 8, conflict-free
#define WP   40                  // ws pitch (floats): conflict-free LDS.64 pairs
#define WS_STAGE (MT * WP)       // 10240 floats
#define XS_STAGE (KC * XP)       // 8448 floats

__device__ float wprep[16 * 512 * 32];   // [k-chunk][row][pos], tf32-RNA-rounded

static __device__ __forceinline__ float tf32r(float x) {
    float r; asm("cvt.rna.tf32.f32 %0, %1;" : "=f"(r) : "f"(x)); return r;
}
static __device__ __forceinline__ uint32_t smem_u32(const void* p) {
    uint32_t a;
    asm("{ .reg .u64 t; cvta.to.shared.u64 t, %1; cvt.u32.u64 %0, t; }" : "=r"(a) : "l"(p));
    return a;
}

#define CP_ASYNC16(d, s) asm volatile("cp.async.cg.shared.global [%0], [%1], 16;" :: "r"(d), "l"(s))
#define CP_COMMIT()      asm volatile("cp.async.commit_group;" ::: "memory")
#define CP_WAIT1()       asm volatile("cp.async.wait_group 1;" ::: "memory")

#define MMA_TF32(d0,d1,d2,d3, a0,a1,a2,a3, b0,b1)                              \
    asm volatile("mma.sync.aligned.m16n8k8.row.col.f32.tf32.tf32.f32 "         \
        "{%0,%1,%2,%3}, {%4,%5,%6,%7}, {%8,%9}, {%0,%1,%2,%3};"                \
        : "+f"(d0), "+f"(d1), "+f"(d2), "+f"(d3)                               \
        : "r"(a0), "r"(a1), "r"(a2), "r"(a3), "r"(b0), "r"(b1))

// prep: tf32-RNA-round W, store k-pair-permuted per 32-k chunk:
// within each 8-k group order [k0,k4,k1,k5,k2,k6,k3,k7] so (k,k+4) adjacent.
__global__ void prep_w_kernel(const float* __restrict__ w) {
    const int idx = blockIdx.x * 256 + threadIdx.x;
    const int row = idx >> 9;
    const int k   = idx & 511;
    const int kk  = k & 31;
    const int pos = ((kk >> 3) << 3) + 2 * (kk & 3) + ((kk & 7) >> 2);
    wprep[(((size_t)(k >> 5) * 512) + row) * 32 + pos] = tf32r(w[idx]);
}

__global__ __launch_bounds__(512, 1)
void fft_hmma_kernel(const float* __restrict__ xr,
                     const float* __restrict__ xi,
                     float* __restrict__ out) {
    extern __shared__ float smem[];
    float* ws = smem;
    float* xs = smem + NSTG * WS_STAGE;
    const uint32_t ws_u32 = smem_u32(ws);

    const int tid  = threadIdx.x;
    const int lane = tid & 31;
    const int wid  = tid >> 5;
    const int wr   = wid & 3;                 // M-warp: 4 x 64 = 256
    const int wc   = wid >> 2;                // N-warp: 4 x 64 = 256
    const int ty   = lane >> 2;
    const int tx   = lane & 3;

    const int c0 = blockIdx.x * NT;
    const int by = blockIdx.y;                // s-plane; o0 = by*256
    const int o0 = by * MT;
    const int b  = blockIdx.z;

    // X fill roles: 2048 float4 per stage / 512 thr = 4 each
    const int x_c4 = (tid & 63) * 4;          // column group 0..252
    const int x_kw = tid >> 6;                // 0..7, k strided by 8
    const size_t xoff = (size_t)b * NFFT * HW + c0 + x_c4;

    const float* wsrc0 = wprep + (size_t)o0 * 32;

    float acc[4][8][4];
    #pragma unroll
    for (int mt = 0; mt < 4; mt++)
        #pragma unroll
        for (int nt = 0; nt < 8; nt++)
            #pragma unroll
            for (int q = 0; q < 4; q++) acc[mt][nt][q] = 0.0f;

    float4 px[4];

    // ---- prologue: W chunks 0,1 via cp.async; X chunks 0,1 via registers ----
    #pragma unroll
    for (int cpre = 0; cpre < 2; cpre++) {
        const float* src = wsrc0 + (size_t)cpre * 512 * 32;
        const uint32_t dst = ws_u32 + cpre * (WS_STAGE * 4);
        #pragma unroll
        for (int p = 0; p < 4; p++) {
            const int idx = p * 512 + tid;
            const int r = idx >> 3, j = idx & 7;
            CP_ASYNC16(dst + r * (WP * 4) + j * 16, src + r * 32 + j * 4);
        }
        CP_COMMIT();
    }
    #pragma unroll
    for (int cpre = 0; cpre < 2; cpre++) {
        const float* xsrcp = xr + xoff + (size_t)(cpre * KC) * HW;
        #pragma unroll
        for (int p = 0; p < 4; p++)
            px[p] = *(const float4*)(xsrcp + (size_t)(p * 8 + x_kw) * HW);
        float* xd = xs + cpre * XS_STAGE;
        #pragma unroll
        for (int p = 0; p < 4; p++) {
            float4 v = px[p];
            v.x = tf32r(v.x); v.y = tf32r(v.y); v.z = tf32r(v.z); v.w = tf32r(v.w);
            *(float4*)(xd + (p * 8 + x_kw) * XP + x_c4) = v;
        }
    }

    const int abase = (wr * 64 + ty) * WP + 2 * tx;     // + mt*16*WP + kk
    const int bbase = tx * XP + wc * 64 + ty;           // + kk*XP + nt*8

    for (int i = 0; i < 16; i++) {
        CP_WAIT1();
        __syncthreads();

        const int ki = i + 2;
        if (ki < 16) {
            const float* src = wsrc0 + (size_t)ki * 512 * 32;
            const uint32_t dst = ws_u32 + (ki % NSTG) * (WS_STAGE * 4);
            #pragma unroll
            for (int p = 0; p < 4; p++) {
                const int idx = p * 512 + tid;
                const int r = idx >> 3, j = idx & 7;
                CP_ASYNC16(dst + r * (WP * 4) + j * 16, src + r * 32 + j * 4);
            }
            const float* xsrcp = ((ki < 8) ? xr : xi) + xoff + (size_t)((ki & 7) * KC) * HW;
            #pragma unroll
            for (int p = 0; p < 4; p++)
                px[p] = *(const float4*)(xsrcp + (size_t)(p * 8 + x_kw) * HW);
        }
        CP_COMMIT();

        // ---- compute chunk i ----
        const float* wst = ws + (i % NSTG) * WS_STAGE;
        const float* xst = xs + (i % NSTG) * XS_STAGE;
        #pragma unroll
        for (int kk = 0; kk < KC; kk += 8) {
            float2 a2[4][2];
            #pragma unroll
            for (int mt = 0; mt < 4; mt++) {
                const float* ap = wst + abase + mt * (16 * WP) + kk;
                a2[mt][0] = *(const float2*)ap;               // rows ty   : (k, k+4)
                a2[mt][1] = *(const float2*)(ap + 8 * WP);    // rows ty+8 : (k, k+4)
            }
            uint32_t bf[8][2];
            #pragma unroll
            for (int nt = 0; nt < 8; nt++) {
                const float* bp = xst + bbase + kk * XP + nt * 8;
                bf[nt][0] = __float_as_uint(bp[0]);
                bf[nt][1] = __float_as_uint(bp[4 * XP]);
            }
            #pragma unroll
            for (int mt = 0; mt < 4; mt++) {
                const uint32_t a0 = __float_as_uint(a2[mt][0].x);
                const uint32_t a1 = __float_as_uint(a2[mt][1].x);
                const uint32_t a2r = __float_as_uint(a2[mt][0].y);
                const uint32_t a3 = __float_as_uint(a2[mt][1].y);
                #pragma unroll
                for (int nt = 0; nt < 8; nt++)
                    MMA_TF32(acc[mt][nt][0], acc[mt][nt][1], acc[mt][nt][2], acc[mt][nt][3],
                             a0, a1, a2r, a3, bf[nt][0], bf[nt][1]);
            }
        }

        // ---- X STS chunk ki ----
        if (ki < 16) {
            float* xd = xs + (ki % NSTG) * XS_STAGE;
            #pragma unroll
            for (int p = 0; p < 4; p++) {
                float4 v = px[p];
                v.x = tf32r(v.x); v.y = tf32r(v.y); v.z = tf32r(v.z); v.w = tf32r(v.w);
                *(float4*)(xd + (p * 8 + x_kw) * XP + x_c4) = v;
            }
        }
    }

    // ---- epilogue: direct STG.64 ----
    float* outp = out + ((size_t)(by * 4 + b) * NFFT) * (size_t)HW + c0 + wc * 64;
    #pragma unroll
    for (int mt = 0; mt < 4; mt++) {
        const int r0 = wr * 64 + mt * 16 + ty;
        #pragma unroll
        for (int nt = 0; nt < 8; nt++) {
            const int col = nt * 8 + tx * 2;
            float2 v0 = make_float2(acc[mt][nt][0], acc[mt][nt][1]);
            float2 v1 = make_float2(acc[mt][nt][2], acc[mt][nt][3]);
            *(float2*)(outp + (size_t)r0 * HW + col)       = v0;
            *(float2*)(outp + (size_t)(r0 + 8) * HW + col) = v1;
        }
    }
}

extern "C" void kernel_launch(void* const* d_in, const int* in_sizes, int n_in,
                              void* d_out, int out_size) {
    const float* xr = nullptr;
    const float* xi = nullptr;
    const float* w  = nullptr;
    for (int i = 0; i < n_in; i++) {
        if (in_sizes[i] == 4 * NFFT * HW) {
            if (!xr)      xr = (const float*)d_in[i];
            else if (!xi) xi = (const float*)d_in[i];
        } else if (in_sizes[i] == KTOT * KTOT) {
            w = (const float*)d_in[i];
        }
    }
    float* out = (float*)d_out;

    prep_w_kernel<<<1024, 256>>>(w);

    const int smem_bytes = NSTG * (WS_STAGE + XS_STAGE) * 4;   // 224,256
    cudaFuncSetAttribute(fft_hmma_kernel, cudaFuncAttributeMaxDynamicSharedMemorySize, smem_bytes);
    dim3 grid(HW / NT, 2, 4);   // (256, 2, 4)
    fft_hmma_kernel<<<grid, 512, smem_bytes>>>(xr, xi, out);
}

// round 11
// speedup vs baseline: 3.0807x; 3.0807x over previous
#include <cuda_runtime.h>
#include <cstdint>

// out[s,b,o,hw] = sum_k adc_real[b,k,hw]*W[s*256+o,k] + adc_imag[b,k,hw]*W[s*256+o,256+k]
// GEMM D[512, 4*65536] = W[512,512] * X[512,*] via mma.sync tf32 HMMA.
// R11: 2 CTAs/SM (256 thr, CTA tile 128x128, warp 64x32) so the two CTAs'
// pipelines interleave and cover each other's barrier gaps. o-tile is the
// fastest grid dim so the 4 CTAs sharing an X c-tile hit L2. 3-stage cp.async
// W (pre-rounded, k-pair-permuted), register X fill (RNA tf32), STG.64 epi.

#define NFFT 256
#define HW   65536
#define KTOT 512
#define KC   32
#define MT   128                 // o rows per CTA
#define NT   128                 // hw cols per CTA
#define NSTG 3
#define XP   136                 // xs pitch (floats), conflict-free (verified)
#define WP   40                  // ws pitch (floats), conflict-free LDS.64 pairs
#define WS_STAGE (MT * WP)       // 5120 floats = 20480 B
#define XS_STAGE (KC * XP)       // 4352 floats = 17408 B

__device__ float wprep[16 * 512 * 32];   // [k-chunk][row][pos], tf32-RNA-rounded

static __device__ __forceinline__ float tf32r(float x) {
    float r; asm("cvt.rna.tf32.f32 %0, %1;" : "=f"(r) : "f"(x)); return r;
}
static __device__ __forceinline__ uint32_t smem_u32(const void* p) {
    uint32_t a;
    asm("{ .reg .u64 t; cvta.to.shared.u64 t, %1; cvt.u32.u64 %0, t; }" : "=r"(a) : "l"(p));
    return a;
}

#define CP_ASYNC16(d, s) asm volatile("cp.async.cg.shared.global [%0], [%1], 16;" :: "r"(d), "l"(s))
#define CP_COMMIT()      asm volatile("cp.async.commit_group;" ::: "memory")
#define CP_WAIT1()       asm volatile("cp.async.wait_group 1;" ::: "memory")

#define MMA_TF32(d0,d1,d2,d3, a0,a1,a2,a3, b0,b1)                              \
    asm volatile("mma.sync.aligned.m16n8k8.row.col.f32.tf32.tf32.f32 "         \
        "{%0,%1,%2,%3}, {%4,%5,%6,%7}, {%8,%9}, {%0,%1,%2,%3};"                \
        : "+f"(d0), "+f"(d1), "+f"(d2), "+f"(d3)                               \
        : "r"(a0), "r"(a1), "r"(a2), "r"(a3), "r"(b0), "r"(b1))

// prep: tf32-RNA-round W, store k-pair-permuted per 32-k chunk:
// within each 8-k group order [k0,k4,k1,k5,k2,k6,k3,k7] so (k,k+4) adjacent.
__global__ void prep_w_kernel(const float* __restrict__ w) {
    const int idx = blockIdx.x * 256 + threadIdx.x;
    const int row = idx >> 9;
    const int k   = idx & 511;
    const int kk  = k & 31;
    const int pos = ((kk >> 3) << 3) + 2 * (kk & 3) + ((kk & 7) >> 2);
    wprep[(((size_t)(k >> 5) * 512) + row) * 32 + pos] = tf32r(w[idx]);
}

__global__ __launch_bounds__(256, 2)
void fft_hmma_kernel(const float* __restrict__ xr,
                     const float* __restrict__ xi,
                     float* __restrict__ out) {
    extern __shared__ float smem[];
    float* ws = smem;
    float* xs = smem + NSTG * WS_STAGE;
    const uint32_t ws_u32 = smem_u32(ws);

    const int tid  = threadIdx.x;
    const int lane = tid & 31;
    const int wid  = tid >> 5;
    const int wr   = wid & 1;                 // M-warp: 2 x 64 = 128
    const int wc   = wid >> 1;                // N-warp: 4 x 32 = 128
    const int ty   = lane >> 2;
    const int tx   = lane & 3;

    const int ot = blockIdx.x;                // o-tile 0..3 (fastest: L2 X share)
    const int o0 = ot * MT;
    const int c0 = blockIdx.y * NT;
    const int b  = blockIdx.z;

    // X fill roles (R7-proven): 1024 float4 per stage / 256 thr = 4 each
    const int x_c4 = (tid & 31) * 4;
    const int x_kw = tid >> 5;                // 0..7, k strided by 8
    const size_t xoff = (size_t)b * NFFT * HW + c0 + x_c4;

    const float* wsrc0 = wprep + (size_t)o0 * 32;

    float acc[4][4][4];
    #pragma unroll
    for (int mt = 0; mt < 4; mt++)
        #pragma unroll
        for (int nt = 0; nt < 4; nt++)
            #pragma unroll
            for (int q = 0; q < 4; q++) acc[mt][nt][q] = 0.0f;

    float4 px[4];

    // ---- prologue: W chunks 0,1 via cp.async; X chunks 0,1 via registers ----
    #pragma unroll
    for (int cpre = 0; cpre < 2; cpre++) {
        const float* src = wsrc0 + (size_t)cpre * 512 * 32;
        const uint32_t dst = ws_u32 + cpre * (WS_STAGE * 4);
        #pragma unroll
        for (int p = 0; p < 4; p++) {           // 1024 16B pieces / 256 thr
            const int idx = p * 256 + tid;
            const int r = idx >> 3, j = idx & 7;
            CP_ASYNC16(dst + r * (WP * 4) + j * 16, src + r * 32 + j * 4);
        }
        CP_COMMIT();
    }
    #pragma unroll
    for (int cpre = 0; cpre < 2; cpre++) {
        const float* xsrcp = xr + xoff + (size_t)(cpre * KC) * HW;
        #pragma unroll
        for (int p = 0; p < 4; p++)
            px[p] = *(const float4*)(xsrcp + (size_t)(p * 8 + x_kw) * HW);
        float* xd = xs + cpre * XS_STAGE;
        #pragma unroll
        for (int p = 0; p < 4; p++) {
            float4 v = px[p];
            v.x = tf32r(v.x); v.y = tf32r(v.y); v.z = tf32r(v.z); v.w = tf32r(v.w);
            *(float4*)(xd + (p * 8 + x_kw) * XP + x_c4) = v;
        }
    }

    const int abase = (wr * 64 + ty) * WP + 2 * tx;     // + mt*16*WP + kk
    const int bbase = tx * XP + wc * 32 + ty;           // + kk*XP + nt*8

    for (int i = 0; i < 16; i++) {
        CP_WAIT1();
        __syncthreads();

        const int ki = i + 2;
        if (ki < 16) {
            const float* src = wsrc0 + (size_t)ki * 512 * 32;
            const uint32_t dst = ws_u32 + (ki % NSTG) * (WS_STAGE * 4);
            #pragma unroll
            for (int p = 0; p < 4; p++) {
                const int idx = p * 256 + tid;
                const int r = idx >> 3, j = idx & 7;
                CP_ASYNC16(dst + r * (WP * 4) + j * 16, src + r * 32 + j * 4);
            }
            const float* xsrcp = ((ki < 8) ? xr : xi) + xoff + (size_t)((ki & 7) * KC) * HW;
            #pragma unroll
            for (int p = 0; p < 4; p++)
                px[p] = *(const float4*)(xsrcp + (size_t)(p * 8 + x_kw) * HW);
        }
        CP_COMMIT();

        // ---- compute chunk i from stage i%3 ----
        const float* wst = ws + (i % NSTG) * WS_STAGE;
        const float* xst = xs + (i % NSTG) * XS_STAGE;
        #pragma unroll
        for (int kk = 0; kk < KC; kk += 8) {
            float2 a2[4][2];
            #pragma unroll
            for (int mt = 0; mt < 4; mt++) {
                const float* ap = wst + abase + mt * (16 * WP) + kk;
                a2[mt][0] = *(const float2*)ap;               // row ty   : (k, k+4)
                a2[mt][1] = *(const float2*)(ap + 8 * WP);    // row ty+8 : (k, k+4)
            }
            uint32_t bf[4][2];
            #pragma unroll
            for (int nt = 0; nt < 4; nt++) {
                const float* bp = xst + bbase + kk * XP + nt * 8;
                bf[nt][0] = __float_as_uint(bp[0]);
                bf[nt][1] = __float_as_uint(bp[4 * XP]);
            }
            #pragma unroll
            for (int mt = 0; mt < 4; mt++) {
                const uint32_t a0 = __float_as_uint(a2[mt][0].x);
                const uint32_t a1 = __float_as_uint(a2[mt][1].x);
                const uint32_t a2r = __float_as_uint(a2[mt][0].y);
                const uint32_t a3 = __float_as_uint(a2[mt][1].y);
                #pragma unroll
                for (int nt = 0; nt < 4; nt++)
                    MMA_TF32(acc[mt][nt][0], acc[mt][nt][1], acc[mt][nt][2], acc[mt][nt][3],
                             a0, a1, a2r, a3, bf[nt][0], bf[nt][1]);
            }
        }

        // ---- X STS chunk ki -> stage ki%3 ----
        if (ki < 16) {
            float* xd = xs + (ki % NSTG) * XS_STAGE;
            #pragma unroll
            for (int p = 0; p < 4; p++) {
                float4 v = px[p];
                v.x = tf32r(v.x); v.y = tf32r(v.y); v.z = tf32r(v.z); v.w = tf32r(v.w);
                *(float4*)(xd + (p * 8 + x_kw) * XP + x_c4) = v;
            }
        }
    }

    // ---- epilogue: direct STG.64 ----
    // global O = o0 + local; s-plane = ot>>1, o-in-plane base = (ot&1)*128
    float* outp = out + ((size_t)((ot >> 1) * 4 + b) * NFFT + (ot & 1) * MT) * (size_t)HW
                + c0 + wc * 32;
    #pragma unroll
    for (int mt = 0; mt < 4; mt++) {
        const int r0 = wr * 64 + mt * 16 + ty;
        #pragma unroll
        for (int nt = 0; nt < 4; nt++) {
            const int col = nt * 8 + tx * 2;
            float2 v0 = make_float2(acc[mt][nt][0], acc[mt][nt][1]);
            float2 v1 = make_float2(acc[mt][nt][2], acc[mt][nt][3]);
            *(float2*)(outp + (size_t)r0 * HW + col)       = v0;
            *(float2*)(outp + (size_t)(r0 + 8) * HW + col) = v1;
        }
    }
}

extern "C" void kernel_launch(void* const* d_in, const int* in_sizes, int n_in,
                              void* d_out, int out_size) {
    const float* xr = nullptr;
    const float* xi = nullptr;
    const float* w  = nullptr;
    for (int i = 0; i < n_in; i++) {
        if (in_sizes[i] == 4 * NFFT * HW) {
            if (!xr)      xr = (const float*)d_in[i];
            else if (!xi) xi = (const float*)d_in[i];
        } else if (in_sizes[i] == KTOT * KTOT) {
            w = (const float*)d_in[i];
        }
    }
    float* out = (float*)d_out;

    prep_w_kernel<<<1024, 256>>>(w);

    const int smem_bytes = NSTG * (WS_STAGE + XS_STAGE) * 4;   // 113,664 -> 2 CTAs/SM
    cudaFuncSetAttribute(fft_hmma_kernel, cudaFuncAttributeMaxDynamicSharedMemorySize, smem_bytes);
    dim3 grid(KTOT / MT, HW / NT, 4);   // (4, 512, 4): o-tile fastest for L2 X reuse
    fft_hmma_kernel<<<grid, 256, smem_bytes>>>(xr, xi, out);
}

// round 12
// speedup vs baseline: 3.2914x; 1.0684x over previous
#include <cuda_runtime.h>
#include <cstdint>

// out[s,b,o,hw] = sum_k adc_real[b,k,hw]*W[s*256+o,k] + adc_imag[b,k,hw]*W[s*256+o,256+k]
// GEMM D[512, 4*65536] = W[512,512] * X[512,*] via mma.sync tf32 HMMA.
// R12: R9 geometry (16 warps, warp tile 64x32, CTA 256x128, 3-stage) with the
// issue port stripped to LDS+MMA: X staged by cp.async straight from gmem
// (no cvt / no STS / no LDG tracking; HW tf32 truncation on X), W pre-rounded
// (RNA) + k-pair-permuted offline, per-warp kk phase rotation to desync
// LDS/MMA bursts across warps.

#define NFFT 256
#define HW   65536
#define KTOT 512
#define KC   32
#define MT   256
#define NT   128
#define NSTG 3
#define XP   136                 // xs pitch (floats); XP*4=544 B, 16B-aligned rows
#define WP   40                  // ws pitch (floats), conflict-free LDS.64 pairs
#define WS_STAGE (MT * WP)       // 10240 floats
#define XS_STAGE (KC * XP)       // 4352 floats

__device__ float wprep[16 * 512 * 32];   // [k-chunk][row][pos], tf32-RNA-rounded

static __device__ __forceinline__ float tf32r(float x) {
    float r; asm("cvt.rna.tf32.f32 %0, %1;" : "=f"(r) : "f"(x)); return r;
}
static __device__ __forceinline__ uint32_t smem_u32(const void* p) {
    uint32_t a;
    asm("{ .reg .u64 t; cvta.to.shared.u64 t, %1; cvt.u32.u64 %0, t; }" : "=r"(a) : "l"(p));
    return a;
}

#define CP_ASYNC16(d, s) asm volatile("cp.async.cg.shared.global [%0], [%1], 16;" :: "r"(d), "l"(s))
#define CP_COMMIT()      asm volatile("cp.async.commit_group;" ::: "memory")
#define CP_WAIT1()       asm volatile("cp.async.wait_group 1;" ::: "memory")

#define MMA_TF32(d0,d1,d2,d3, a0,a1,a2,a3, b0,b1)                              \
    asm volatile("mma.sync.aligned.m16n8k8.row.col.f32.tf32.tf32.f32 "         \
        "{%0,%1,%2,%3}, {%4,%5,%6,%7}, {%8,%9}, {%0,%1,%2,%3};"                \
        : "+f"(d0), "+f"(d1), "+f"(d2), "+f"(d3)                               \
        : "r"(a0), "r"(a1), "r"(a2), "r"(a3), "r"(b0), "r"(b1))

// prep: tf32-RNA-round W, store k-pair-permuted per 32-k chunk:
// within each 8-k group order [k0,k4,k1,k5,k2,k6,k3,k7] so (k,k+4) adjacent.
__global__ void prep_w_kernel(const float* __restrict__ w) {
    const int idx = blockIdx.x * 256 + threadIdx.x;
    const int row = idx >> 9;
    const int k   = idx & 511;
    const int kk  = k & 31;
    const int pos = ((kk >> 3) << 3) + 2 * (kk & 3) + ((kk & 7) >> 2);
    wprep[(((size_t)(k >> 5) * 512) + row) * 32 + pos] = tf32r(w[idx]);
}

__global__ __launch_bounds__(512, 1)
void fft_hmma_kernel(const float* __restrict__ xr,
                     const float* __restrict__ xi,
                     float* __restrict__ out) {
    extern __shared__ float smem[];
    float* ws = smem;
    float* xs = smem + NSTG * WS_STAGE;
    const uint32_t ws_u32 = smem_u32(ws);
    const uint32_t xs_u32 = smem_u32(xs);

    const int tid  = threadIdx.x;
    const int lane = tid & 31;
    const int wid  = tid >> 5;
    const int wr   = wid & 3;                 // M-warp: 4 x 64 = 256
    const int wc   = wid >> 2;                // N-warp: 4 x 32 = 128
    const int ty   = lane >> 2;
    const int tx   = lane & 3;

    const int c0 = blockIdx.x * NT;
    const int by = blockIdx.y;                // s-plane; o0 = by*256
    const int o0 = by * MT;
    const int b  = blockIdx.z;

    // cp.async piece roles
    const int x_k   = tid >> 5;               // +16 for p=1: rows 0..31
    const int x_c16 = tid & 31;               // 16B piece along c (32 x 16B = 512B row)
    const size_t xbase = (size_t)b * NFFT * HW + c0;

    const float* wsrc0 = wprep + (size_t)o0 * 32;

    float acc[4][4][4];
    #pragma unroll
    for (int mt = 0; mt < 4; mt++)
        #pragma unroll
        for (int nt = 0; nt < 4; nt++)
            #pragma unroll
            for (int q = 0; q < 4; q++) acc[mt][nt][q] = 0.0f;

    // ---- prologue: chunks 0,1 for W and X via cp.async ----
    #pragma unroll
    for (int cpre = 0; cpre < 2; cpre++) {
        const float* src = wsrc0 + (size_t)cpre * 512 * 32;
        const uint32_t wdst = ws_u32 + cpre * (WS_STAGE * 4);
        #pragma unroll
        for (int p = 0; p < 4; p++) {          // 2048 16B pieces / 512 thr
            const int idx = p * 512 + tid;
            const int r = idx >> 3, j = idx & 7;
            CP_ASYNC16(wdst + r * (WP * 4) + j * 16, src + r * 32 + j * 4);
        }
        const float* xsrcp = xr + xbase + (size_t)(cpre * KC) * HW;
        const uint32_t xdst = xs_u32 + cpre * (XS_STAGE * 4);
        #pragma unroll
        for (int p = 0; p < 2; p++) {          // 1024 16B pieces / 512 thr
            const int k = x_k + p * 16;
            CP_ASYNC16(xdst + k * (XP * 4) + x_c16 * 16,
                       xsrcp + (size_t)k * HW + x_c16 * 4);
        }
        CP_COMMIT();
    }

    const int abase = (wr * 64 + ty) * WP + 2 * tx;     // + mt*16*WP + kk
    const int bbase = tx * XP + wc * 32 + ty;           // + kk*XP + nt*8

    for (int i = 0; i < 16; i++) {
        CP_WAIT1();
        __syncthreads();

        const int ki = i + 2;
        if (ki < 16) {
            const float* src = wsrc0 + (size_t)ki * 512 * 32;
            const uint32_t wdst = ws_u32 + (ki % NSTG) * (WS_STAGE * 4);
            #pragma unroll
            for (int p = 0; p < 4; p++) {
                const int idx = p * 512 + tid;
                const int r = idx >> 3, j = idx & 7;
                CP_ASYNC16(wdst + r * (WP * 4) + j * 16, src + r * 32 + j * 4);
            }
            const float* xsrcp = ((ki < 8) ? xr : xi) + xbase + (size_t)((ki & 7) * KC) * HW;
            const uint32_t xdst = xs_u32 + (ki % NSTG) * (XS_STAGE * 4);
            #pragma unroll
            for (int p = 0; p < 2; p++) {
                const int k = x_k + p * 16;
                CP_ASYNC16(xdst + k * (XP * 4) + x_c16 * 16,
                           xsrcp + (size_t)k * HW + x_c16 * 4);
            }
        }
        CP_COMMIT();

        // ---- compute chunk i from stage i%3, kk phase rotated per warp ----
        const float* wst = ws + (i % NSTG) * WS_STAGE;
        const float* xst = xs + (i % NSTG) * XS_STAGE;
        #pragma unroll
        for (int j = 0; j < 4; j++) {
            const int kk = ((j + wid) & 3) << 3;
            float2 a2[4][2];
            #pragma unroll
            for (int mt = 0; mt < 4; mt++) {
                const float* ap = wst + abase + mt * (16 * WP) + kk;
                a2[mt][0] = *(const float2*)ap;               // row ty   : (k, k+4)
                a2[mt][1] = *(const float2*)(ap + 8 * WP);    // row ty+8 : (k, k+4)
            }
            uint32_t bf[4][2];
            #pragma unroll
            for (int nt = 0; nt < 4; nt++) {
                const float* bp = xst + bbase + kk * XP + nt * 8;
                bf[nt][0] = __float_as_uint(bp[0]);
                bf[nt][1] = __float_as_uint(bp[4 * XP]);
            }
            #pragma unroll
            for (int mt = 0; mt < 4; mt++) {
                const uint32_t a0 = __float_as_uint(a2[mt][0].x);
                const uint32_t a1 = __float_as_uint(a2[mt][1].x);
                const uint32_t a2r = __float_as_uint(a2[mt][0].y);
                const uint32_t a3 = __float_as_uint(a2[mt][1].y);
                #pragma unroll
                for (int nt = 0; nt < 4; nt++)
                    MMA_TF32(acc[mt][nt][0], acc[mt][nt][1], acc[mt][nt][2], acc[mt][nt][3],
                             a0, a1, a2r, a3, bf[nt][0], bf[nt][1]);
            }
        }
    }

    // ---- epilogue: direct STG.64 ----
    float* outp = out + ((size_t)(by * 4 + b) * NFFT) * (size_t)HW + c0 + wc * 32;
    #pragma unroll
    for (int mt = 0; mt < 4; mt++) {
        const int r0 = wr * 64 + mt * 16 + ty;
        #pragma unroll
        for (int nt = 0; nt < 4; nt++) {
            const int col = nt * 8 + tx * 2;
            float2 v0 = make_float2(acc[mt][nt][0], acc[mt][nt][1]);
            float2 v1 = make_float2(acc[mt][nt][2], acc[mt][nt][3]);
            *(float2*)(outp + (size_t)r0 * HW + col)       = v0;
            *(float2*)(outp + (size_t)(r0 + 8) * HW + col) = v1;
        }
    }
}

extern "C" void kernel_launch(void* const* d_in, const int* in_sizes, int n_in,
                              void* d_out, int out_size) {
    const float* xr = nullptr;
    const float* xi = nullptr;
    const float* w  = nullptr;
    for (int i = 0; i < n_in; i++) {
        if (in_sizes[i] == 4 * NFFT * HW) {
            if (!xr)      xr = (const float*)d_in[i];
            else if (!xi) xi = (const float*)d_in[i];
        } else if (in_sizes[i] == KTOT * KTOT) {
            w = (const float*)d_in[i];
        }
    }
    float* out = (float*)d_out;

    prep_w_kernel<<<1024, 256>>>(w);

    const int smem_bytes = NSTG * (WS_STAGE + XS_STAGE) * 4;   // 175,104
    cudaFuncSetAttribute(fft_hmma_kernel, cudaFuncAttributeMaxDynamicSharedMemorySize, smem_bytes);
    dim3 grid(HW / NT, 2, 4);   // (512, 2, 4)
    fft_hmma_kernel<<<grid, 512, smem_bytes>>>(xr, xi, out);
}